// round 1
// baseline (speedup 1.0000x reference)
#include <cuda_runtime.h>
#include <math.h>

#define D   128
#define HH  2
#define MAXM 100000
#define MAXN 50000
#define MAXE 1000000

// ---------------- scratch (device globals; re-initialized every launch) -------------
__device__ float g_u[MAXM * D];          // transformed user features
__device__ float g_i[MAXN * D];          // transformed item features
__device__ float g_u_src[MAXM * HH];     // u . a_u_src[h]   (src scores for u2i)
__device__ float g_u_dst[MAXM * HH];     // u . a_i_dst[h]   (dst scores for i2u)
__device__ float g_i_src[MAXN * HH];     // i . a_i_src[h]   (src scores for i2u)
__device__ float g_i_dst[MAXN * HH];     // i . a_u_dst[h]   (dst scores for u2i)
__device__ float g_denU[MAXM * HH];      // softmax denominators per user row, per head
__device__ float g_denI[MAXN * HH];
__device__ int   g_cntU[MAXM];
__device__ int   g_offU[MAXM];
__device__ int   g_curU[MAXM];
__device__ int   g_cntI[MAXN];
__device__ int   g_offI[MAXN];
__device__ int   g_curI[MAXN];
__device__ int   g_scolU[MAXE];          // row-grouped neighbor column ids
__device__ float g_swU[MAXE];            // row-grouped fused head-mean attention weight
__device__ int   g_scolI[MAXE];
__device__ float g_swI[MAXE];
__device__ int   g_cursor[2];

// ---------------- GEMM: Y[M,128] = X[M,128] @ W[128,128] + b --------------------
// 256 threads: thread (c = t&127, h = t>>7) holds W[h*64 .. h*64+63][c] in registers.
// 32 input rows staged in smem per block; 8-row register blocking; halves combined via smem.
__global__ __launch_bounds__(256) void gemm128(const float* __restrict__ X,
                                               const float* __restrict__ W,
                                               const float* __restrict__ bias,
                                               float* __restrict__ Y, int M)
{
    __shared__ float4 s_in[32][32];   // 32 rows x 128 floats
    __shared__ float  s_red[8][128];  // upper-half partial sums

    int t = threadIdx.x;
    int c = t & 127;
    int h = t >> 7;

    float w[64];
#pragma unroll
    for (int k = 0; k < 64; k++) w[k] = W[(h * 64 + k) * D + c];
    float bv = bias[c];

    int row0 = blockIdx.x * 32;
    const float4* X4 = (const float4*)X;
    for (int idx = t; idx < 32 * 32; idx += 256) {
        int r = idx >> 5, q = idx & 31;
        int row = row0 + r;
        s_in[r][q] = (row < M) ? X4[(size_t)row * 32 + q] : make_float4(0.f, 0.f, 0.f, 0.f);
    }
    __syncthreads();

    for (int g = 0; g < 32; g += 8) {
        float acc[8];
#pragma unroll
        for (int r = 0; r < 8; r++) acc[r] = 0.f;
#pragma unroll
        for (int k4 = 0; k4 < 16; k4++) {
#pragma unroll
            for (int r = 0; r < 8; r++) {
                float4 x = s_in[g + r][h * 16 + k4];
                acc[r] += x.x * w[k4 * 4 + 0];
                acc[r] += x.y * w[k4 * 4 + 1];
                acc[r] += x.z * w[k4 * 4 + 2];
                acc[r] += x.w * w[k4 * 4 + 3];
            }
        }
        if (h == 1) {
#pragma unroll
            for (int r = 0; r < 8; r++) s_red[r][c] = acc[r];
        }
        __syncthreads();
        if (h == 0) {
#pragma unroll
            for (int r = 0; r < 8; r++) {
                int row = row0 + g + r;
                if (row < M) Y[(size_t)row * D + c] = acc[r] + s_red[r][c] + bv;
            }
        }
        __syncthreads();
    }
}

// ---------------- per-node attention scalars: 4 dot products per node ----------------
__global__ __launch_bounds__(256) void node_scores(const float* __restrict__ feat, int n,
                                                   const float* __restrict__ aA,   // H*D
                                                   const float* __restrict__ aB,   // H*D
                                                   float* __restrict__ outA,
                                                   float* __restrict__ outB)
{
    int lane  = threadIdx.x & 31;
    int warp  = (blockIdx.x * blockDim.x + threadIdx.x) >> 5;
    int nwarp = (gridDim.x * blockDim.x) >> 5;
    const float4* f4 = (const float4*)feat;
    float4 a0 = ((const float4*)aA)[lane];
    float4 a1 = ((const float4*)aA)[32 + lane];
    float4 b0 = ((const float4*)aB)[lane];
    float4 b1 = ((const float4*)aB)[32 + lane];

    for (int node = warp; node < n; node += nwarp) {
        float4 x = f4[(size_t)node * 32 + lane];
        float d0 = x.x * a0.x + x.y * a0.y + x.z * a0.z + x.w * a0.w;
        float d1 = x.x * a1.x + x.y * a1.y + x.z * a1.z + x.w * a1.w;
        float d2 = x.x * b0.x + x.y * b0.y + x.z * b0.z + x.w * b0.w;
        float d3 = x.x * b1.x + x.y * b1.y + x.z * b1.z + x.w * b1.w;
#pragma unroll
        for (int s = 16; s; s >>= 1) {
            d0 += __shfl_xor_sync(0xffffffffu, d0, s);
            d1 += __shfl_xor_sync(0xffffffffu, d1, s);
            d2 += __shfl_xor_sync(0xffffffffu, d2, s);
            d3 += __shfl_xor_sync(0xffffffffu, d3, s);
        }
        if (lane == 0) {
            outA[node * 2 + 0] = d0;
            outA[node * 2 + 1] = d1;
            outB[node * 2 + 0] = d2;
            outB[node * 2 + 1] = d3;
        }
    }
}

__device__ __forceinline__ float lrelu(float x) { return x > 0.f ? x : 0.2f * x; }

// ---------------- edge pass 1: softmax denominators + per-row counts ----------------
__global__ __launch_bounds__(256) void edge_pass1(const int* __restrict__ row,
                                                  const int* __restrict__ col,
                                                  const float* __restrict__ ssrc,
                                                  const float* __restrict__ sdst,
                                                  float* __restrict__ denom,
                                                  int* __restrict__ cnt, int E)
{
    int e = blockIdx.x * blockDim.x + threadIdx.x;
    int stride = gridDim.x * blockDim.x;
    for (; e < E; e += stride) {
        int r = row[e], c = col[e];
        float2 s = ((const float2*)ssrc)[r];
        float2 d = ((const float2*)sdst)[c];
        float e0 = __expf(lrelu(s.x + d.x));
        float e1 = __expf(lrelu(s.y + d.y));
        atomicAdd(&denom[r * 2 + 0], e0);
        atomicAdd(&denom[r * 2 + 1], e1);
        atomicAdd(&cnt[r], 1);
    }
}

// ---------------- per-row slab offsets (order-free; atomic cursor) ----------------
__global__ __launch_bounds__(256) void build_offsets(const int* __restrict__ cnt,
                                                     int* __restrict__ off,
                                                     int* __restrict__ cur, int n,
                                                     int* __restrict__ cursor)
{
    int i = blockIdx.x * blockDim.x + threadIdx.x;
    int stride = gridDim.x * blockDim.x;
    for (; i < n; i += stride) {
        int cc = cnt[i];
        int o = atomicAdd(cursor, cc);
        off[i] = o;
        cur[i] = o;
    }
}

// ---------------- edge pass 2: fused head-mean weight + scatter into row slabs -------
__global__ __launch_bounds__(256) void edge_pass2(const int* __restrict__ row,
                                                  const int* __restrict__ col,
                                                  const float* __restrict__ ssrc,
                                                  const float* __restrict__ sdst,
                                                  const float* __restrict__ denom,
                                                  int* __restrict__ cur,
                                                  int* __restrict__ scol,
                                                  float* __restrict__ sw, int E)
{
    int e = blockIdx.x * blockDim.x + threadIdx.x;
    int stride = gridDim.x * blockDim.x;
    for (; e < E; e += stride) {
        int r = row[e], c = col[e];
        float2 s  = ((const float2*)ssrc)[r];
        float2 d  = ((const float2*)sdst)[c];
        float2 dn = ((const float2*)denom)[r];
        float e0 = __expf(lrelu(s.x + d.x));
        float e1 = __expf(lrelu(s.y + d.y));
        float wv = 0.5f * (e0 / dn.x + e1 / dn.y);
        int pos = atomicAdd(&cur[r], 1);
        scol[pos] = c;
        sw[pos]   = wv;
    }
}

// ---------------- aggregation: warp per output row, atomic-free, ELU epilogue -------
__global__ __launch_bounds__(256) void aggregate(const int* __restrict__ off,
                                                 const int* __restrict__ cnt,
                                                 const int* __restrict__ scol,
                                                 const float* __restrict__ sw,
                                                 const float* __restrict__ feat,
                                                 float* __restrict__ out, int nrows)
{
    int lane  = threadIdx.x & 31;
    int warp  = (blockIdx.x * blockDim.x + threadIdx.x) >> 5;
    int nwarp = (gridDim.x * blockDim.x) >> 5;
    const float4* f4 = (const float4*)feat;

    for (int rowi = warp; rowi < nrows; rowi += nwarp) {
        int o = off[rowi];
        int n = cnt[rowi];
        float4 acc = make_float4(0.f, 0.f, 0.f, 0.f);
        for (int j = 0; j < n; j++) {
            int   c  = scol[o + j];
            float wv = sw[o + j];
            float4 v = f4[(size_t)c * 32 + lane];
            acc.x += wv * v.x;
            acc.y += wv * v.y;
            acc.z += wv * v.z;
            acc.w += wv * v.w;
        }
        acc.x = acc.x > 0.f ? acc.x : expm1f(acc.x);
        acc.y = acc.y > 0.f ? acc.y : expm1f(acc.y);
        acc.z = acc.z > 0.f ? acc.z : expm1f(acc.z);
        acc.w = acc.w > 0.f ? acc.w : expm1f(acc.w);
        ((float4*)out)[(size_t)rowi * 32 + lane] = acc;
    }
}

// ---------------------------------- host launcher ----------------------------------
extern "C" void kernel_launch(void* const* d_in, const int* in_sizes, int n_in,
                              void* d_out, int out_size)
{
    const float* u_prev  = (const float*)d_in[0];
    const float* i_prev  = (const float*)d_in[1];
    const float* w_user  = (const float*)d_in[2];
    const float* b_user  = (const float*)d_in[3];
    const float* w_item  = (const float*)d_in[4];
    const float* b_item  = (const float*)d_in[5];
    const float* a_u_src = (const float*)d_in[6];
    const float* a_u_dst = (const float*)d_in[7];
    const float* a_i_src = (const float*)d_in[8];
    const float* a_i_dst = (const float*)d_in[9];
    const int* u2i_row = (const int*)d_in[10];
    const int* u2i_col = (const int*)d_in[11];
    const int* i2u_row = (const int*)d_in[12];
    const int* i2u_col = (const int*)d_in[13];
    float* out = (float*)d_out;

    int M = in_sizes[0] / D;
    int N = in_sizes[1] / D;
    int E = in_sizes[10];

    float *p_u, *p_i, *p_u_src, *p_u_dst, *p_i_src, *p_i_dst, *p_denU, *p_denI, *p_swU, *p_swI;
    int *p_cntU, *p_offU, *p_curU, *p_cntI, *p_offI, *p_curI, *p_scolU, *p_scolI, *p_cursor;
    cudaGetSymbolAddress((void**)&p_u,     g_u);
    cudaGetSymbolAddress((void**)&p_i,     g_i);
    cudaGetSymbolAddress((void**)&p_u_src, g_u_src);
    cudaGetSymbolAddress((void**)&p_u_dst, g_u_dst);
    cudaGetSymbolAddress((void**)&p_i_src, g_i_src);
    cudaGetSymbolAddress((void**)&p_i_dst, g_i_dst);
    cudaGetSymbolAddress((void**)&p_denU,  g_denU);
    cudaGetSymbolAddress((void**)&p_denI,  g_denI);
    cudaGetSymbolAddress((void**)&p_cntU,  g_cntU);
    cudaGetSymbolAddress((void**)&p_offU,  g_offU);
    cudaGetSymbolAddress((void**)&p_curU,  g_curU);
    cudaGetSymbolAddress((void**)&p_cntI,  g_cntI);
    cudaGetSymbolAddress((void**)&p_offI,  g_offI);
    cudaGetSymbolAddress((void**)&p_curI,  g_curI);
    cudaGetSymbolAddress((void**)&p_scolU, g_scolU);
    cudaGetSymbolAddress((void**)&p_swU,   g_swU);
    cudaGetSymbolAddress((void**)&p_scolI, g_scolI);
    cudaGetSymbolAddress((void**)&p_swI,   g_swI);
    cudaGetSymbolAddress((void**)&p_cursor, g_cursor);

    // per-replay scratch re-init (graph replays must be self-contained)
    cudaMemsetAsync(p_denU, 0, (size_t)M * HH * sizeof(float));
    cudaMemsetAsync(p_denI, 0, (size_t)N * HH * sizeof(float));
    cudaMemsetAsync(p_cntU, 0, (size_t)M * sizeof(int));
    cudaMemsetAsync(p_cntI, 0, (size_t)N * sizeof(int));
    cudaMemsetAsync(p_cursor, 0, 2 * sizeof(int));

    // 1) feature transforms
    gemm128<<<(M + 31) / 32, 256>>>(u_prev, w_user, b_user, p_u, M);
    gemm128<<<(N + 31) / 32, 256>>>(i_prev, w_item, b_item, p_i, N);

    // 2) per-node attention scalars
    node_scores<<<(M * 32 + 255) / 256, 256>>>(p_u, M, a_u_src, a_i_dst, p_u_src, p_u_dst);
    node_scores<<<(N * 32 + 255) / 256, 256>>>(p_i, N, a_i_src, a_u_dst, p_i_src, p_i_dst);

    // 3) denominators + counts
    int eb = (E + 255) / 256;
    edge_pass1<<<eb, 256>>>(u2i_row, u2i_col, p_u_src, p_i_dst, p_denU, p_cntU, E);
    edge_pass1<<<eb, 256>>>(i2u_row, i2u_col, p_i_src, p_u_dst, p_denI, p_cntI, E);

    // 4) row slab offsets
    build_offsets<<<(M + 255) / 256, 256>>>(p_cntU, p_offU, p_curU, M, p_cursor);
    build_offsets<<<(N + 255) / 256, 256>>>(p_cntI, p_offI, p_curI, N, p_cursor + 1);

    // 5) weights scattered into row-grouped slabs
    edge_pass2<<<eb, 256>>>(u2i_row, u2i_col, p_u_src, p_i_dst, p_denU, p_curU, p_scolU, p_swU, E);
    edge_pass2<<<eb, 256>>>(i2u_row, i2u_col, p_i_src, p_u_dst, p_denI, p_curI, p_scolI, p_swI, E);

    // 6) atomic-free aggregation + ELU, writing both output halves
    aggregate<<<(M * 32 + 255) / 256, 256>>>(p_offU, p_cntU, p_scolU, p_swU, p_i, out, M);
    aggregate<<<(N * 32 + 255) / 256, 256>>>(p_offI, p_cntI, p_scolI, p_swI, p_u, out + (size_t)M * D, N);
}

// round 3
// speedup vs baseline: 1.0918x; 1.0918x over previous
#include <cuda_runtime.h>
#include <mma.h>
#include <math.h>

using namespace nvcuda;

#define D    128
#define HH   2
#define MAXM 100000
#define MAXN 50000
#define MAXE 1000000

#define BM   64      // gemm rows per block
#define LDA  36      // sA leading dim (32 + 4 pad)
#define LDB  132     // sB / sY leading dim (128 + 4 pad)

// ---------------- scratch (device globals; re-initialized every launch) -------------
__device__ float g_u[MAXM * D];
__device__ float g_i[MAXN * D];
__device__ float g_u_src[MAXM * HH];
__device__ float g_u_dst[MAXM * HH];
__device__ float g_i_src[MAXN * HH];
__device__ float g_i_dst[MAXN * HH];
__device__ float g_denU[MAXM * HH];
__device__ float g_denI[MAXN * HH];
__device__ int   g_cntU[MAXM];
__device__ int   g_offU[MAXM];
__device__ int   g_curU[MAXM];
__device__ int   g_cntI[MAXN];
__device__ int   g_offI[MAXN];
__device__ int   g_curI[MAXN];
__device__ int2  g_packU[MAXE];   // (col, weight-bits) grouped by row
__device__ int2  g_packI[MAXE];
__device__ int   g_cursor[2];

// ------- 3xTF32 tensor-core GEMM + fused attention-score epilogue -------------------
// Y[M,128] = X[M,128] @ W[128,128] + b ; also outS[m][h]=Y[m]·aS[h], outD[m][h]=Y[m]·aD[h]
// Split-precision: A = a_hi + a_lo, B = b_hi + b_lo (tf32); acc += hh + hl + lh -> ~fp32.
// 256 threads = 8 warps; block tile 64x128; warp tile 16x64 (wm=warp/2, wn=warp%2).
__global__ __launch_bounds__(256) void gemm_tc(const float* __restrict__ X,
                                               const float* __restrict__ W,
                                               const float* __restrict__ bias,
                                               const float* __restrict__ aS,  // H*D
                                               const float* __restrict__ aD,  // H*D
                                               float* __restrict__ Y,
                                               float* __restrict__ outS,
                                               float* __restrict__ outD, int M)
{
    // pooled smem: during K loop  [sA 64x36 | sB 32x132];  after, aliased as sY 64x132
    __shared__ float pool[BM * LDB];           // 33792 B
    float* sA = pool;                          // 64*36   = 2304 floats
    float* sB = pool + BM * LDA;               // 32*132  = 4224 floats (total 6528 < 8448)
    float* sY = pool;

    int t    = threadIdx.x;
    int warp = t >> 5;
    int lane = t & 31;
    int wm   = warp >> 1;          // 0..3 -> row offset wm*16
    int wn   = warp & 1;           // 0..1 -> col offset wn*64
    int row0 = blockIdx.x * BM;

    wmma::fragment<wmma::accumulator, 16, 16, 8, float> acc[4];
#pragma unroll
    for (int f = 0; f < 4; f++) wmma::fill_fragment(acc[f], 0.0f);

    const float4* X4 = (const float4*)X;
    const float4* W4 = (const float4*)W;

    for (int kc = 0; kc < 4; kc++) {           // K chunks of 32
        // load A chunk: rows row0..row0+63, cols kc*32..+32  (8 float4 per row)
#pragma unroll
        for (int it = 0; it < 2; it++) {
            int i = t + it * 256;              // 0..511
            int r = i >> 3, q = i & 7;
            int row = row0 + r;
            float4 v = (row < M) ? X4[(size_t)row * 32 + kc * 8 + q]
                                 : make_float4(0.f, 0.f, 0.f, 0.f);
            *(float4*)&sA[r * LDA + q * 4] = v;
        }
        // load B chunk: W rows kc*32..+32, all 128 cols (32 float4 per row)
#pragma unroll
        for (int it = 0; it < 4; it++) {
            int i = t + it * 256;              // 0..1023
            int r = i >> 5, q = i & 31;
            *(float4*)&sB[r * LDB + q * 4] = W4[(size_t)(kc * 32 + r) * 32 + q];
        }
        __syncthreads();

#pragma unroll
        for (int ks = 0; ks < 4; ks++) {       // k-steps of 8
            wmma::fragment<wmma::matrix_a, 16, 16, 8, wmma::precision::tf32, wmma::row_major> a_hi, a_lo;
            wmma::load_matrix_sync(a_hi, &sA[wm * 16 * LDA + ks * 8], LDA);
#pragma unroll
            for (int i = 0; i < a_hi.num_elements; i++) {
                float v  = a_hi.x[i];
                float hi = wmma::__float_to_tf32(v);
                a_hi.x[i] = hi;
                a_lo.x[i] = wmma::__float_to_tf32(v - hi);
            }
#pragma unroll
            for (int f = 0; f < 4; f++) {
                wmma::fragment<wmma::matrix_b, 16, 16, 8, wmma::precision::tf32, wmma::row_major> b_hi, b_lo;
                wmma::load_matrix_sync(b_hi, &sB[ks * 8 * LDB + wn * 64 + f * 16], LDB);
#pragma unroll
                for (int i = 0; i < b_hi.num_elements; i++) {
                    float v  = b_hi.x[i];
                    float hi = wmma::__float_to_tf32(v);
                    b_hi.x[i] = hi;
                    b_lo.x[i] = wmma::__float_to_tf32(v - hi);
                }
                wmma::mma_sync(acc[f], a_lo, b_hi, acc[f]);
                wmma::mma_sync(acc[f], a_hi, b_lo, acc[f]);
                wmma::mma_sync(acc[f], a_hi, b_hi, acc[f]);
            }
        }
        __syncthreads();
    }

    // spill accumulators to smem tile (aliases sA/sB — dead now)
#pragma unroll
    for (int f = 0; f < 4; f++)
        wmma::store_matrix_sync(&sY[wm * 16 * LDB + wn * 64 + f * 16], acc[f], LDB, wmma::mem_row_major);
    __syncthreads();

    // add bias into smem tile
#pragma unroll
    for (int it = 0; it < 8; it++) {
        int i = t + it * 256;                  // 0..2047
        int r = i >> 5, q = i & 31;
        float4* p = (float4*)&sY[r * LDB + q * 4];
        float4 b4 = ((const float4*)bias)[q];
        float4 v = *p;
        v.x += b4.x; v.y += b4.y; v.z += b4.z; v.w += b4.w;
        *p = v;
    }
    __syncthreads();

    // write Y
#pragma unroll
    for (int it = 0; it < 8; it++) {
        int i = t + it * 256;
        int r = i >> 5, q = i & 31;
        int row = row0 + r;
        if (row < M)
            ((float4*)Y)[(size_t)row * 32 + q] = *(float4*)&sY[r * LDB + q * 4];
    }

    // fused attention scalars: warp w handles rows w*8 .. w*8+7
    {
        float4 s0 = ((const float4*)aS)[lane];
        float4 s1 = ((const float4*)aS)[32 + lane];
        float4 d0 = ((const float4*)aD)[lane];
        float4 d1 = ((const float4*)aD)[32 + lane];
#pragma unroll
        for (int rr = 0; rr < 8; rr++) {
            int r = warp * 8 + rr;
            int row = row0 + r;
            float4 y = *(float4*)&sY[r * LDB + lane * 4];
            float p0 = y.x * s0.x + y.y * s0.y + y.z * s0.z + y.w * s0.w;
            float p1 = y.x * s1.x + y.y * s1.y + y.z * s1.z + y.w * s1.w;
            float p2 = y.x * d0.x + y.y * d0.y + y.z * d0.z + y.w * d0.w;
            float p3 = y.x * d1.x + y.y * d1.y + y.z * d1.z + y.w * d1.w;
#pragma unroll
            for (int s = 16; s; s >>= 1) {
                p0 += __shfl_xor_sync(0xffffffffu, p0, s);
                p1 += __shfl_xor_sync(0xffffffffu, p1, s);
                p2 += __shfl_xor_sync(0xffffffffu, p2, s);
                p3 += __shfl_xor_sync(0xffffffffu, p3, s);
            }
            if (lane == 0 && row < M) {
                outS[row * 2 + 0] = p0;
                outS[row * 2 + 1] = p1;
                outD[row * 2 + 0] = p2;
                outD[row * 2 + 1] = p3;
            }
        }
    }
}

__device__ __forceinline__ float lrelu(float x) { return x > 0.f ? x : 0.2f * x; }

// ---------------- edge pass 1: softmax denominators + per-row counts ----------------
__global__ __launch_bounds__(256) void edge_pass1(const int* __restrict__ row,
                                                  const int* __restrict__ col,
                                                  const float* __restrict__ ssrc,
                                                  const float* __restrict__ sdst,
                                                  float* __restrict__ denom,
                                                  int* __restrict__ cnt, int E)
{
    int e = blockIdx.x * blockDim.x + threadIdx.x;
    int stride = gridDim.x * blockDim.x;
    for (; e < E; e += stride) {
        int r = row[e], c = col[e];
        float2 s = ((const float2*)ssrc)[r];
        float2 d = ((const float2*)sdst)[c];
        float e0 = __expf(lrelu(s.x + d.x));
        float e1 = __expf(lrelu(s.y + d.y));
        atomicAdd(&denom[r * 2 + 0], e0);
        atomicAdd(&denom[r * 2 + 1], e1);
        atomicAdd(&cnt[r], 1);
    }
}

// ---------------- per-row slab offsets (order-free; atomic cursor) ----------------
__global__ __launch_bounds__(256) void build_offsets(const int* __restrict__ cnt,
                                                     int* __restrict__ off,
                                                     int* __restrict__ cur, int n,
                                                     int* __restrict__ cursor)
{
    int i = blockIdx.x * blockDim.x + threadIdx.x;
    int stride = gridDim.x * blockDim.x;
    for (; i < n; i += stride) {
        int cc = cnt[i];
        int o = atomicAdd(cursor, cc);
        off[i] = o;
        cur[i] = o;
    }
}

// ---------------- edge pass 2: fused head-mean weight + packed scatter --------------
__global__ __launch_bounds__(256) void edge_pass2(const int* __restrict__ row,
                                                  const int* __restrict__ col,
                                                  const float* __restrict__ ssrc,
                                                  const float* __restrict__ sdst,
                                                  const float* __restrict__ denom,
                                                  int* __restrict__ cur,
                                                  int2* __restrict__ pack, int E)
{
    int e = blockIdx.x * blockDim.x + threadIdx.x;
    int stride = gridDim.x * blockDim.x;
    for (; e < E; e += stride) {
        int r = row[e], c = col[e];
        float2 s  = ((const float2*)ssrc)[r];
        float2 d  = ((const float2*)sdst)[c];
        float2 dn = ((const float2*)denom)[r];
        float e0 = __expf(lrelu(s.x + d.x));
        float e1 = __expf(lrelu(s.y + d.y));
        float wv = 0.5f * (e0 / dn.x + e1 / dn.y);
        int pos = atomicAdd(&cur[r], 1);
        pack[pos] = make_int2(c, __float_as_int(wv));
    }
}

// ---------------- aggregation: warp per output row, atomic-free, ELU epilogue -------
__global__ __launch_bounds__(256) void aggregate(const int* __restrict__ off,
                                                 const int* __restrict__ cnt,
                                                 const int2* __restrict__ pack,
                                                 const float* __restrict__ feat,
                                                 float* __restrict__ out, int nrows)
{
    int lane  = threadIdx.x & 31;
    int warp  = (blockIdx.x * blockDim.x + threadIdx.x) >> 5;
    int nwarp = (gridDim.x * blockDim.x) >> 5;
    const float4* f4 = (const float4*)feat;

    for (int rowi = warp; rowi < nrows; rowi += nwarp) {
        int o = off[rowi];
        int n = cnt[rowi];
        float4 acc = make_float4(0.f, 0.f, 0.f, 0.f);
        int j = 0;
        for (; j + 1 < n; j += 2) {
            int2 p0 = pack[o + j];
            int2 p1 = pack[o + j + 1];
            float4 v0 = f4[(size_t)p0.x * 32 + lane];
            float4 v1 = f4[(size_t)p1.x * 32 + lane];
            float w0 = __int_as_float(p0.y);
            float w1 = __int_as_float(p1.y);
            acc.x += w0 * v0.x + w1 * v1.x;
            acc.y += w0 * v0.y + w1 * v1.y;
            acc.z += w0 * v0.z + w1 * v1.z;
            acc.w += w0 * v0.w + w1 * v1.w;
        }
        if (j < n) {
            int2 p0 = pack[o + j];
            float4 v0 = f4[(size_t)p0.x * 32 + lane];
            float w0 = __int_as_float(p0.y);
            acc.x += w0 * v0.x;
            acc.y += w0 * v0.y;
            acc.z += w0 * v0.z;
            acc.w += w0 * v0.w;
        }
        acc.x = acc.x > 0.f ? acc.x : expm1f(acc.x);
        acc.y = acc.y > 0.f ? acc.y : expm1f(acc.y);
        acc.z = acc.z > 0.f ? acc.z : expm1f(acc.z);
        acc.w = acc.w > 0.f ? acc.w : expm1f(acc.w);
        ((float4*)out)[(size_t)rowi * 32 + lane] = acc;
    }
}

// ---------------------------------- host launcher ----------------------------------
extern "C" void kernel_launch(void* const* d_in, const int* in_sizes, int n_in,
                              void* d_out, int out_size)
{
    const float* u_prev  = (const float*)d_in[0];
    const float* i_prev  = (const float*)d_in[1];
    const float* w_user  = (const float*)d_in[2];
    const float* b_user  = (const float*)d_in[3];
    const float* w_item  = (const float*)d_in[4];
    const float* b_item  = (const float*)d_in[5];
    const float* a_u_src = (const float*)d_in[6];
    const float* a_u_dst = (const float*)d_in[7];
    const float* a_i_src = (const float*)d_in[8];
    const float* a_i_dst = (const float*)d_in[9];
    const int* u2i_row = (const int*)d_in[10];
    const int* u2i_col = (const int*)d_in[11];
    const int* i2u_row = (const int*)d_in[12];
    const int* i2u_col = (const int*)d_in[13];
    float* out = (float*)d_out;

    int M = in_sizes[0] / D;
    int N = in_sizes[1] / D;
    int E = in_sizes[10];

    float *p_u, *p_i, *p_u_src, *p_u_dst, *p_i_src, *p_i_dst, *p_denU, *p_denI;
    int *p_cntU, *p_offU, *p_curU, *p_cntI, *p_offI, *p_curI, *p_cursor;
    int2 *p_packU, *p_packI;
    cudaGetSymbolAddress((void**)&p_u,     g_u);
    cudaGetSymbolAddress((void**)&p_i,     g_i);
    cudaGetSymbolAddress((void**)&p_u_src, g_u_src);
    cudaGetSymbolAddress((void**)&p_u_dst, g_u_dst);
    cudaGetSymbolAddress((void**)&p_i_src, g_i_src);
    cudaGetSymbolAddress((void**)&p_i_dst, g_i_dst);
    cudaGetSymbolAddress((void**)&p_denU,  g_denU);
    cudaGetSymbolAddress((void**)&p_denI,  g_denI);
    cudaGetSymbolAddress((void**)&p_cntU,  g_cntU);
    cudaGetSymbolAddress((void**)&p_offU,  g_offU);
    cudaGetSymbolAddress((void**)&p_curU,  g_curU);
    cudaGetSymbolAddress((void**)&p_cntI,  g_cntI);
    cudaGetSymbolAddress((void**)&p_offI,  g_offI);
    cudaGetSymbolAddress((void**)&p_curI,  g_curI);
    cudaGetSymbolAddress((void**)&p_packU, g_packU);
    cudaGetSymbolAddress((void**)&p_packI, g_packI);
    cudaGetSymbolAddress((void**)&p_cursor, g_cursor);

    // per-replay scratch re-init
    cudaMemsetAsync(p_denU, 0, (size_t)M * HH * sizeof(float));
    cudaMemsetAsync(p_denI, 0, (size_t)N * HH * sizeof(float));
    cudaMemsetAsync(p_cntU, 0, (size_t)M * sizeof(int));
    cudaMemsetAsync(p_cntI, 0, (size_t)N * sizeof(int));
    cudaMemsetAsync(p_cursor, 0, 2 * sizeof(int));

    // 1) tensor-core feature transforms + fused attention scalars
    gemm_tc<<<(M + BM - 1) / BM, 256>>>(u_prev, w_user, b_user, a_u_src, a_i_dst,
                                        p_u, p_u_src, p_u_dst, M);
    gemm_tc<<<(N + BM - 1) / BM, 256>>>(i_prev, w_item, b_item, a_i_src, a_u_dst,
                                        p_i, p_i_src, p_i_dst, N);

    // 2) denominators + counts
    int eb = (E + 255) / 256;
    edge_pass1<<<eb, 256>>>(u2i_row, u2i_col, p_u_src, p_i_dst, p_denU, p_cntU, E);
    edge_pass1<<<eb, 256>>>(i2u_row, i2u_col, p_i_src, p_u_dst, p_denI, p_cntI, E);

    // 3) row slab offsets
    build_offsets<<<(M + 255) / 256, 256>>>(p_cntU, p_offU, p_curU, M, p_cursor);
    build_offsets<<<(N + 255) / 256, 256>>>(p_cntI, p_offI, p_curI, N, p_cursor + 1);

    // 4) weights scattered into row-grouped packed slabs
    edge_pass2<<<eb, 256>>>(u2i_row, u2i_col, p_u_src, p_i_dst, p_denU, p_curU, p_packU, E);
    edge_pass2<<<eb, 256>>>(i2u_row, i2u_col, p_i_src, p_u_dst, p_denI, p_curI, p_packI, E);

    // 5) atomic-free aggregation + ELU
    aggregate<<<(M * 32 + 255) / 256, 256>>>(p_offU, p_cntU, p_packU, p_i, out, M);
    aggregate<<<(N * 32 + 255) / 256, 256>>>(p_offI, p_cntI, p_packI, p_u, out + (size_t)M * D, N);
}